// round 6
// baseline (speedup 1.0000x reference)
#include <cuda_runtime.h>
#include <math.h>
#include <stdint.h>

#define VOCAB 32000
#define EMB 256
#define HID 256
#define BATCH 64
#define SEQT 2048

// Scratch: V[v][j] = sum_e emb[v][e]*W_ih[e][j] + b_ih[j] + b_hh[j]  (32 MB, L2-resident)
__device__ float g_V[VOCAB * HID];

// ---------------------------------------------------------------------------
// f32x2 packed helpers (PTX-only; ptxas won't auto-fuse)
// ---------------------------------------------------------------------------
__device__ __forceinline__ unsigned long long pack2(float lo, float hi) {
    unsigned long long r;
    asm("mov.b64 %0, {%1, %2};" : "=l"(r) : "f"(lo), "f"(hi));
    return r;
}
__device__ __forceinline__ void fma2(unsigned long long& acc,
                                     unsigned long long a, unsigned long long b) {
    asm("fma.rn.f32x2 %0, %1, %2, %0;" : "+l"(acc) : "l"(a), "l"(b));
}
__device__ __forceinline__ unsigned long long add2(unsigned long long a,
                                                   unsigned long long b) {
    unsigned long long r;
    asm("add.rn.f32x2 %0, %1, %2;" : "=l"(r) : "l"(a), "l"(b));
    return r;
}
__device__ __forceinline__ void unpack2(unsigned long long v, float& lo, float& hi) {
    asm("mov.b64 {%0, %1}, %2;" : "=f"(lo), "=f"(hi) : "l"(v));
}

// Cluster / mbarrier helpers
__device__ __forceinline__ uint32_t smem_u32(const void* p) {
    uint32_t a;
    asm("{ .reg .u64 t; cvta.to.shared.u64 t, %1; cvt.u32.u64 %0, t; }"
        : "=r"(a) : "l"(p));
    return a;
}
__device__ __forceinline__ uint32_t mapa_peer(uint32_t addr, uint32_t rank) {
    uint32_t r;
    asm("mapa.shared::cluster.u32 %0, %1, %2;" : "=r"(r) : "r"(addr), "r"(rank));
    return r;
}
__device__ __forceinline__ void mbar_init(uint32_t addr, uint32_t count) {
    asm volatile("mbarrier.init.shared.b64 [%0], %1;" :: "r"(addr), "r"(count) : "memory");
}
__device__ __forceinline__ void mbar_expect_tx(uint32_t addr, uint32_t bytes) {
    asm volatile("mbarrier.arrive.expect_tx.shared.b64 _, [%0], %1;"
                 :: "r"(addr), "r"(bytes) : "memory");
}
// Remote store fused with peer-mbar tx completion (data + signal in one op)
__device__ __forceinline__ void st_async_f32(uint32_t remote_addr, float v,
                                             uint32_t remote_mbar) {
    asm volatile(
        "st.async.shared::cluster.mbarrier::complete_tx::bytes.b32 [%0], %1, [%2];"
        :: "r"(remote_addr), "r"(__float_as_int(v)), "r"(remote_mbar) : "memory");
}
__device__ __forceinline__ void mbar_wait_parity(uint32_t addr, uint32_t parity) {
    uint32_t done;
    asm volatile(
        "{\n\t"
        ".reg .pred p;\n\t"
        "mbarrier.try_wait.parity.acquire.cluster.shared::cta.b64 p, [%1], %2;\n\t"
        "selp.b32 %0, 1, 0, p;\n\t"
        "}" : "=r"(done) : "r"(addr), "r"(parity) : "memory");
    if (!done) {
        asm volatile(
            "{\n\t"
            ".reg .pred P1;\n\t"
            "WL_%=:\n\t"
            "mbarrier.try_wait.parity.acquire.cluster.shared::cta.b64 P1, [%0], %1, 0x989680;\n\t"
            "@P1 bra.uni WD_%=;\n\t"
            "bra.uni WL_%=;\n\t"
            "WD_%=:\n\t"
            "}" :: "r"(addr), "r"(parity) : "memory");
    }
}
#define CLUSTER_SYNC() do { \
    asm volatile("barrier.cluster.arrive.aligned;" ::: "memory"); \
    asm volatile("barrier.cluster.wait.aligned;" ::: "memory"); \
} while (0)

// ---------------------------------------------------------------------------
// Kernel 1: vocab projection GEMM  [32000,256] x [256,256] + bias  (f32x2)
// ---------------------------------------------------------------------------
__global__ void __launch_bounds__(256) vocab_proj_kernel(
    const float* __restrict__ emb, const float* __restrict__ W_ih,
    const float* __restrict__ b_ih, const float* __restrict__ b_hh)
{
    __shared__ float As_T[32][68];
    const int row0 = blockIdx.x * 64;
    const int j = threadIdx.x;

    const float bias = b_ih[j] + b_hh[j];

    unsigned long long acc[32];
#pragma unroll
    for (int p = 0; p < 32; p++) acc[p] = 0ull;

#pragma unroll 1
    for (int k0 = 0; k0 < EMB; k0 += 32) {
        __syncthreads();
#pragma unroll
        for (int it = 0; it < 8; it++) {
            int idx = it * 256 + threadIdx.x;
            int r  = idx >> 5;
            int kk = idx & 31;
            As_T[kk][r] = emb[(size_t)(row0 + r) * EMB + (k0 + kk)];
        }
        __syncthreads();

        float wt[32];
#pragma unroll
        for (int kk = 0; kk < 32; kk++)
            wt[kk] = W_ih[(size_t)(k0 + kk) * HID + j];

#pragma unroll
        for (int kk = 0; kk < 32; kk++) {
            unsigned long long ws = pack2(wt[kk], wt[kk]);
#pragma unroll
            for (int rp2 = 0; rp2 < 16; rp2++) {
                ulonglong2 av = *(const ulonglong2*)&As_T[kk][4 * rp2];
                fma2(acc[2 * rp2 + 0], av.x, ws);
                fma2(acc[2 * rp2 + 1], av.y, ws);
            }
        }
    }

#pragma unroll
    for (int p = 0; p < 32; p++) {
        float lo, hi;
        unpack2(acc[p], lo, hi);
        g_V[(size_t)(row0 + 2 * p + 0) * HID + j] = lo + bias;
        g_V[(size_t)(row0 + 2 * p + 1) * HID + j] = hi + bias;
    }
}

// ---------------------------------------------------------------------------
// Kernel 2: recurrence, PARTIAL-SUM exchange (h never crosses the cluster).
// CTA r owns h columns / k-range [r*128, r*128+128). Every thread computes
// partial[jg] over the LOCAL k-half only (h is SMEM-local, no wait pre-FMA):
//   thread t: lc = t&127; grp = t>>7 (0 = receiver/own cols, 1 = sender)
//   jg = ((grp ^ rank) << 7) | lc   (global column)
// Senders (warps 4-7, one per SMSP, hi-wid priority -> issue first) st.async
// their partial to the peer's pbuf + mbar tx. Receivers FMA, wait mbar, then
// pre = xv + own_partial + peer_partial -> tanh -> hs[nxt]. One bar/step.
// ---------------------------------------------------------------------------
__global__ void __launch_bounds__(256, 1) __cluster_dims__(2, 1, 1)
rnn_kernel(const int* __restrict__ source, const float* __restrict__ W_hh,
           float* __restrict__ out)
{
    __shared__ float hs[2][128];     // local h half, double-buffered
    __shared__ float pbuf[2][128];   // incoming peer partials, double-buffered
    __shared__ int   src_s[SEQT];
    __shared__ __align__(8) unsigned long long mbar[2];

    const int t   = threadIdx.x;
    const int lc  = t & 127;
    const int grp = t >> 7;          // 0 = receiver, 1 = sender (warps 4-7)
    const int b   = blockIdx.x >> 1;

    uint32_t rank;
    asm("mov.u32 %0, %%cluster_ctarank;" : "=r"(rank));

    const int jg = (((grp ^ (int)rank) & 1) << 7) | lc;  // global output column
    const int k0 = (int)rank * 128;                      // local k-range base

    for (int i = t; i < SEQT; i += 256) src_s[i] = source[b * SEQT + i];

    // W_hh[k0 .. k0+127][jg] register-resident as 64 f32x2
    unsigned long long wreg[64];
#pragma unroll
    for (int i = 0; i < 64; i++)
        wreg[i] = pack2(W_hh[(size_t)(k0 + 2 * i + 0) * HID + jg],
                        W_hh[(size_t)(k0 + 2 * i + 1) * HID + jg]);

    if (t < 128) { hs[0][t] = 0.0f; hs[1][t] = 0.0f; }
    if (t == 0) {
        mbar_init(smem_u32(&mbar[0]), 1);
        mbar_init(smem_u32(&mbar[1]), 1);
        mbar_expect_tx(smem_u32(&mbar[0]), 512);  // pre-arm phase 0 of both
        mbar_expect_tx(smem_u32(&mbar[1]), 512);
    }

    // Sender thread targets: peer's pbuf[buf][lc] + peer's mbar[buf]
    uint32_t peer_pbuf[2], peer_mbar[2], mbar_local[2];
    peer_pbuf[0] = mapa_peer(smem_u32(&pbuf[0][lc]), rank ^ 1u);
    peer_pbuf[1] = mapa_peer(smem_u32(&pbuf[1][lc]), rank ^ 1u);
    peer_mbar[0] = mapa_peer(smem_u32(&mbar[0]), rank ^ 1u);
    peer_mbar[1] = mapa_peer(smem_u32(&mbar[1]), rank ^ 1u);
    mbar_local[0] = smem_u32(&mbar[0]);
    mbar_local[1] = smem_u32(&mbar[1]);

    __syncthreads();
    CLUSTER_SYNC();  // mbar init + expect_tx visible cluster-wide

    float hval = 0.0f;

#pragma unroll 1
    for (int step = 0; step < SEQT; step++) {
        const int cur = step & 1;

        // Receivers prefetch x-projection (L2 gather, consumed ~400cyc later)
        float xv = 0.0f;
        if (grp == 0) xv = g_V[(size_t)src_s[step] * HID + jg];

        // Partial over LOCAL k-half only — no cross-CTA wait before FMA
        const float* hp = &hs[cur][0];
        unsigned long long a0 = 0, a1 = 0, a2 = 0, a3 = 0;
        unsigned long long b0 = 0, b1 = 0, b2 = 0, b3 = 0;
#pragma unroll
        for (int q = 0; q < 32; q += 4) {
            ulonglong2 h0 = *(const ulonglong2*)(hp + 4 * (q + 0));
            ulonglong2 h1 = *(const ulonglong2*)(hp + 4 * (q + 1));
            ulonglong2 h2 = *(const ulonglong2*)(hp + 4 * (q + 2));
            ulonglong2 h3 = *(const ulonglong2*)(hp + 4 * (q + 3));
            fma2(a0, h0.x, wreg[2 * q + 0]); fma2(b0, h0.y, wreg[2 * q + 1]);
            fma2(a1, h1.x, wreg[2 * q + 2]); fma2(b1, h1.y, wreg[2 * q + 3]);
            fma2(a2, h2.x, wreg[2 * q + 4]); fma2(b2, h2.y, wreg[2 * q + 5]);
            fma2(a3, h3.x, wreg[2 * q + 6]); fma2(b3, h3.y, wreg[2 * q + 7]);
        }
        unsigned long long s = add2(add2(add2(a0, a1), add2(a2, a3)),
                                    add2(add2(b0, b1), add2(b2, b3)));
        float lo, hi;
        unpack2(s, lo, hi);
        const float pr = lo + hi;

        if (grp == 1) {
            // Sender: partial for a peer-owned column -> data+signal in one op
            st_async_f32(peer_pbuf[cur], pr, peer_mbar[cur]);
        } else {
            // Receiver: wait for the peer's 128 partials of this step
            mbar_wait_parity(mbar_local[cur], ((uint32_t)step >> 1) & 1u);
            if (t == 0) mbar_expect_tx(mbar_local[cur], 512);  // re-arm next phase

            float pre = xv + pr + pbuf[cur][lc];
            float e = __expf(2.0f * pre);
            hval = 1.0f - __fdividef(2.0f, e + 1.0f);
            hs[cur ^ 1][lc] = hval;   // local-only h store
        }

        __syncthreads();  // hs[nxt] visible to all warps; recycles buffers
    }

    if (grp == 0) out[b * HID + jg] = hval;

    CLUSTER_SYNC();  // keep SMEM/mbar alive for any in-flight peer traffic
}

// ---------------------------------------------------------------------------
extern "C" void kernel_launch(void* const* d_in, const int* in_sizes, int n_in,
                              void* d_out, int out_size)
{
    const int*   source    = (const int*)d_in[0];
    const float* embedding = (const float*)d_in[1];
    const float* W_ih      = (const float*)d_in[2];
    const float* W_hh      = (const float*)d_in[3];
    const float* b_ih      = (const float*)d_in[4];
    const float* b_hh      = (const float*)d_in[5];
    float* out = (float*)d_out;

    vocab_proj_kernel<<<VOCAB / 64, 256>>>(embedding, W_ih, b_ih, b_hh);
    rnn_kernel<<<BATCH * 2, 256>>>(source, W_hh, out);
}